// round 15
// baseline (speedup 1.0000x reference)
#include <cuda_runtime.h>
#include <cuda_fp8.h>
#include <cuda_fp16.h>
#include <cstdint>

#define NP    8192
#define DIM   256                 // elements per row (= bytes per row in fp8)
#define TM    128                 // tile rows
#define TN    256                 // tile cols
#define KC    128                 // fp8 K-chunk: 128B rows
#define NKC   (DIM / KC)          // 2 chunks
#define NTX   (NP / TN)           // 32 tiles in x
#define NT    ((NP / TM) * NTX)   // 2048 tiles

// smem byte offsets: 2 resident chunks, 128B rows, XOR-16B swizzle
#define OFF_A(c)  ((c) * 16384)                  // 128 rows * 128B
#define OFF_B(c)  (32768 + (c) * 32768)          // 256 rows * 128B
#define OFF_SQA   98304                          // 128 floats (512B)
#define OFF_SQB   98816                          // 256 floats (1024B)
#define SMEM_TOT  99840

#define FXSCALE   1099511627776.0                // 2^40

// ---------------- scratch (allocation-free rule) ----------------
__device__ float              g_sq1[NP];
__device__ float              g_sq2[NP];
__device__ unsigned           g_min1[NP];
__device__ unsigned           g_min2[NP];
__device__ uint8_t            g_q1[NP * DIM];
__device__ uint8_t            g_q2[NP * DIM];
__device__ unsigned long long g_fsum = 0;        // fixed-point sum (2^-40 units)
__device__ unsigned           g_done = 0;        // finalize ticket counter

__device__ __forceinline__ uint32_t s2u(const void* p) {
    uint32_t a;
    asm("{ .reg .u64 t; cvta.to.shared.u64 t, %1; cvt.u32.u64 %0, t; }"
        : "=r"(a) : "l"(p));
    return a;
}
__device__ __forceinline__ void cp16(uint32_t dst, const void* src) {
    asm volatile("cp.async.cg.shared.global [%0], [%1], 16;"
                 :: "r"(dst), "l"(__cvta_generic_to_global(src)) : "memory");
}
__device__ __forceinline__ void ldm_x4(uint32_t& r0, uint32_t& r1,
                                       uint32_t& r2, uint32_t& r3, uint32_t a) {
    asm volatile("ldmatrix.sync.aligned.m8n8.x4.shared.b16 {%0,%1,%2,%3}, [%4];"
                 : "=r"(r0), "=r"(r1), "=r"(r2), "=r"(r3) : "r"(a));
}
// fp8 e4m3 MMA, fp32 accumulate. Fragment layout identical to s8 m16n8k32.
__device__ __forceinline__ void mma_fp8(float& c0, float& c1, float& c2, float& c3,
                                        uint32_t a0, uint32_t a1, uint32_t a2, uint32_t a3,
                                        uint32_t b0, uint32_t b1) {
    asm volatile("mma.sync.aligned.m16n8k32.row.col.f32.e4m3.e4m3.f32 "
                 "{%0,%1,%2,%3}, {%4,%5,%6,%7}, {%8,%9}, {%0,%1,%2,%3};"
                 : "+f"(c0), "+f"(c1), "+f"(c2), "+f"(c3)
                 : "r"(a0), "r"(a1), "r"(a2), "r"(a3), "r"(b0), "r"(b1));
}

// quantize a float2 to e4m3, return the dequantized values (what the MMA sees)
__device__ __forceinline__ float2 q8(float2 v, uint32_t& bits16) {
    __nv_fp8x2_e4m3 q(v);
    bits16 = (uint32_t)q.__x;
    __half2_raw hr = __nv_cvt_fp8x2_to_halfraw2(q.__x, __NV_E4M3);
    return __half22float2(*reinterpret_cast<__half2*>(&hr));
}

// ---------------------------------------------------------------------------
// Kernel 1: fp32 -> fp8(e4m3) + norms OF THE QUANTIZED VALUES + min init.
// One warp per row; lane covers 8 consecutive elements (8 bytes out).
// ---------------------------------------------------------------------------
__global__ void prep_kernel(const float* __restrict__ s1,
                            const float* __restrict__ s2) {
    int gw   = (blockIdx.x * blockDim.x + threadIdx.x) >> 5;
    int lane = threadIdx.x & 31;
    bool first = gw < NP;
    int row = gw & (NP - 1);
    const float4* p = reinterpret_cast<const float4*>(
        (first ? s1 : s2) + (size_t)row * DIM);
    uint2* dst = reinterpret_cast<uint2*>(
        (first ? g_q1 : g_q2) + (size_t)row * DIM);

    float4 v0 = p[2 * lane];
    float4 v1 = p[2 * lane + 1];
    uint32_t b0, b1, b2, b3;
    float2 f;
    float s = 0.f;
    f = q8(make_float2(v0.x, v0.y), b0); s += f.x * f.x + f.y * f.y;
    f = q8(make_float2(v0.z, v0.w), b1); s += f.x * f.x + f.y * f.y;
    f = q8(make_float2(v1.x, v1.y), b2); s += f.x * f.x + f.y * f.y;
    f = q8(make_float2(v1.z, v1.w), b3); s += f.x * f.x + f.y * f.y;
    uint2 w;
    w.x = b0 | (b1 << 16);
    w.y = b2 | (b3 << 16);
    dst[lane] = w;

#pragma unroll
    for (int o = 16; o; o >>= 1) s += __shfl_xor_sync(0xffffffffu, s, o);
    if (lane == 0) {
        if (first) { g_sq1[row] = s; g_min1[row] = 0x7f7fffffu; }
        else       { g_sq2[row] = s; g_min2[row] = 0x7f7fffffu; }
    }
}

// ---------------------------------------------------------------------------
// Kernel 2: PERSISTENT fp8 MMA Gram kernel. 128x256 tile, 8 warps (2x4),
// 64x64 warp tile, 2 K-chunks of 128B; prefetch next tile's chunk into the
// buffer just consumed. Geometry/addressing identical to the verified int8
// round-6 kernel; scheduling identical to the round-13 winner.
// ---------------------------------------------------------------------------
__global__ void __launch_bounds__(256, 1)
dist_min_mma_kernel() {
    extern __shared__ char smem[];
    const uint32_t sbp = s2u(smem);
    float* sqa_s = reinterpret_cast<float*>(smem + OFF_SQA);
    float* sqb_s = reinterpret_cast<float*>(smem + OFF_SQB);

    const int tid  = threadIdx.x;
    const int lane = tid & 31;
    const int wid  = tid >> 5;
    const int wm   = wid & 1;          // 64-row slice
    const int wn   = wid >> 1;         // 64-col slice
    const int G    = gridDim.x;

    auto issue_chunk = [&](int tile, int c) {
        int rb = (tile >> 5) * TM;
        int cb = (tile & (NTX - 1)) * TN;
        const uint8_t* ga = g_q1 + (size_t)rb * DIM + c * KC;
        const uint8_t* gb = g_q2 + (size_t)cb * DIM + c * KC;
        uint32_t da = sbp + OFF_A(c), db = sbp + OFF_B(c);
#pragma unroll
        for (int it = 0; it < 4; ++it) {
            int idx = tid + it * 256;           // 0..1023
            int r = idx >> 3, q = idx & 7;
            cp16(da + r * 128 + ((q ^ (r & 7)) << 4), ga + (size_t)r * DIM + q * 16);
        }
#pragma unroll
        for (int it = 0; it < 8; ++it) {
            int idx = tid + it * 256;           // 0..2047
            int r = idx >> 3, q = idx & 7;
            cp16(db + r * 128 + ((q ^ (r & 7)) << 4), gb + (size_t)r * DIM + q * 16);
        }
        asm volatile("cp.async.commit_group;" ::: "memory");
    };

    const int l7  = lane & 7;
    const int l15 = lane & 15;
    const int h   = lane >> 4;                   // 16B-slot half
    const uint32_t a_ro = (uint32_t)(wm * 64 + l15) * 128;
    const uint32_t b_ro = (uint32_t)(wn * 64 + l15) * 128;

#pragma unroll
    for (int c = 0; c < NKC; ++c) issue_chunk(blockIdx.x, c);

    for (int t = blockIdx.x; t < NT; t += G) {
        const int rowBase = (t >> 5) * TM;
        const int colBase = (t & (NTX - 1)) * TN;
        int nt = t + G;
        if (nt >= NT) nt = t;                    // keep group-count math uniform

        if (tid < 128) sqa_s[tid] = g_sq1[rowBase + tid];
        sqb_s[tid] = g_sq2[colBase + tid];

        float acc[4][8][4];
#pragma unroll
        for (int i = 0; i < 4; ++i)
#pragma unroll
            for (int j = 0; j < 8; ++j)
#pragma unroll
                for (int q = 0; q < 4; ++q) acc[i][j][q] = 0.f;

#pragma unroll
        for (int c = 0; c < NKC; ++c) {
            asm volatile("cp.async.wait_group 1;" ::: "memory");
            __syncthreads();

            const uint32_t sa0 = sbp + OFF_A(c) + a_ro;
            const uint32_t sb0 = sbp + OFF_B(c) + b_ro;
#pragma unroll
            for (int ks = 0; ks < 4; ++ks) {     // four k32 steps per 128B chunk
                const uint32_t sw = (uint32_t)(((2 * ks + h) ^ l7) << 4);
                uint32_t a[4][4], bb[4][4];
#pragma unroll
                for (int mt = 0; mt < 4; ++mt)
                    ldm_x4(a[mt][0], a[mt][1], a[mt][2], a[mt][3],
                           sa0 + mt * 2048 + sw);
#pragma unroll
                for (int np = 0; np < 4; ++np)
                    ldm_x4(bb[np][0], bb[np][1], bb[np][2], bb[np][3],
                           sb0 + np * 2048 + sw);
                // bb[np]: r0=b0(j=2np), r1=b0(j=2np+1), r2=b1(j=2np), r3=b1(j=2np+1)
#pragma unroll
                for (int mt = 0; mt < 4; ++mt)
#pragma unroll
                    for (int np = 0; np < 4; ++np) {
                        mma_fp8(acc[mt][2 * np][0], acc[mt][2 * np][1],
                                acc[mt][2 * np][2], acc[mt][2 * np][3],
                                a[mt][0], a[mt][1], a[mt][2], a[mt][3],
                                bb[np][0], bb[np][2]);
                        mma_fp8(acc[mt][2 * np + 1][0], acc[mt][2 * np + 1][1],
                                acc[mt][2 * np + 1][2], acc[mt][2 * np + 1][3],
                                a[mt][0], a[mt][1], a[mt][2], a[mt][3],
                                bb[np][1], bb[np][3]);
                    }
            }
            __syncthreads();
            issue_chunk(nt, c);
        }

        // ---- Epilogue: d^2 + fused row/col mins ----
        const float FMAX = 3.4028235e38f;
        float rmin[4][2];
#pragma unroll
        for (int i = 0; i < 4; ++i) rmin[i][0] = rmin[i][1] = FMAX;
        float cmin[8][2];
#pragma unroll
        for (int j = 0; j < 8; ++j) cmin[j][0] = cmin[j][1] = FMAX;

#pragma unroll
        for (int mt = 0; mt < 4; ++mt) {
            float sqa0 = sqa_s[wm * 64 + mt * 16 + (lane >> 2)];
            float sqa1 = sqa_s[wm * 64 + mt * 16 + (lane >> 2) + 8];
#pragma unroll
            for (int n8 = 0; n8 < 8; ++n8) {
                float sqb0 = sqb_s[wn * 64 + n8 * 8 + 2 * (lane & 3)];
                float sqb1 = sqb_s[wn * 64 + n8 * 8 + 2 * (lane & 3) + 1];
                float d00 = fmaxf(fmaf(-2.f, acc[mt][n8][0], sqa0 + sqb0), 0.f);
                float d01 = fmaxf(fmaf(-2.f, acc[mt][n8][1], sqa0 + sqb1), 0.f);
                float d10 = fmaxf(fmaf(-2.f, acc[mt][n8][2], sqa1 + sqb0), 0.f);
                float d11 = fmaxf(fmaf(-2.f, acc[mt][n8][3], sqa1 + sqb1), 0.f);
                rmin[mt][0] = fminf(rmin[mt][0], fminf(d00, d01));
                rmin[mt][1] = fminf(rmin[mt][1], fminf(d10, d11));
                cmin[n8][0] = fminf(cmin[n8][0], fminf(d00, d10));
                cmin[n8][1] = fminf(cmin[n8][1], fminf(d01, d11));
            }
        }

#pragma unroll
        for (int mt = 0; mt < 4; ++mt)
#pragma unroll
            for (int hh = 0; hh < 2; ++hh) {
                float v = rmin[mt][hh];
                v = fminf(v, __shfl_xor_sync(0xffffffffu, v, 1));
                v = fminf(v, __shfl_xor_sync(0xffffffffu, v, 2));
                if ((lane & 3) == 0)
                    atomicMin(&g_min1[rowBase + wm * 64 + mt * 16 + hh * 8 + (lane >> 2)],
                              __float_as_uint(v));
            }

#pragma unroll
        for (int n8 = 0; n8 < 8; ++n8)
#pragma unroll
            for (int q = 0; q < 2; ++q) {
                float v = cmin[n8][q];
                v = fminf(v, __shfl_xor_sync(0xffffffffu, v, 4));
                v = fminf(v, __shfl_xor_sync(0xffffffffu, v, 8));
                v = fminf(v, __shfl_xor_sync(0xffffffffu, v, 16));
                if (lane < 4)
                    atomicMin(&g_min2[colBase + wn * 64 + n8 * 8 + 2 * lane + q],
                              __float_as_uint(v));
            }

        __syncthreads();   // protect sqa_s/sqb_s (rewritten next iteration)
    }

    asm volatile("cp.async.wait_group 0;" ::: "memory");  // drain before exit
}

// ---------------------------------------------------------------------------
// Kernel 3: parallel finalize (identical to round-13 winner).
// ---------------------------------------------------------------------------
__global__ void finalize_kernel(float* __restrict__ out) {
    __shared__ float red[8];
    const int tid = threadIdx.x;
    const int gid = blockIdx.x * 256 + tid;      // 0..16383
    float v = (gid < NP) ? sqrtf(__uint_as_float(g_min1[gid]))
                         : sqrtf(__uint_as_float(g_min2[gid - NP]));
#pragma unroll
    for (int o = 16; o; o >>= 1) v += __shfl_xor_sync(0xffffffffu, v, o);
    if ((tid & 31) == 0) red[tid >> 5] = v;
    __syncthreads();
    if (tid < 32) {
        float s = (tid < 8) ? red[tid] : 0.f;
#pragma unroll
        for (int o = 4; o; o >>= 1) s += __shfl_xor_sync(0xffffffffu, s, o);
        if (tid == 0) {
            unsigned long long fx =
                (unsigned long long)((double)s * FXSCALE + 0.5);
            atomicAdd(&g_fsum, fx);
            __threadfence();
            unsigned ticket = atomicAdd(&g_done, 1u);
            if (ticket == gridDim.x - 1) {
                unsigned long long tot = atomicAdd(&g_fsum, 0ull);
                out[0] = (float)((double)tot / FXSCALE / (double)NP);
                g_fsum = 0ull;                  // reset for next replay
                g_done = 0u;
            }
        }
    }
}

// ---------------------------------------------------------------------------
extern "C" void kernel_launch(void* const* d_in, const int* in_sizes, int n_in,
                              void* d_out, int out_size) {
    const float* s1 = (const float*)d_in[0];
    const float* s2 = (const float*)d_in[1];

    static int nsm = 0;
    if (nsm == 0) {
        cudaFuncSetAttribute(dist_min_mma_kernel,
                             cudaFuncAttributeMaxDynamicSharedMemorySize, SMEM_TOT);
        cudaDeviceGetAttribute(&nsm, cudaDevAttrMultiProcessorCount, 0);
        if (nsm <= 0) nsm = 148;
    }

    prep_kernel<<<2 * NP / 8, 256>>>(s1, s2);

    dist_min_mma_kernel<<<nsm, 256, SMEM_TOT>>>();

    finalize_kernel<<<2 * NP / 256, 256>>>((float*)d_out);
}

// round 16
// speedup vs baseline: 1.1423x; 1.1423x over previous
#include <cuda_runtime.h>
#include <cuda_bf16.h>
#include <cstdint>

#define NP    8192
#define DIM   256
#define TM    128                 // tile rows
#define TN    256                 // tile cols
#define KC    64                  // bf16 K-chunk: 128B rows
#define NKC   (DIM / KC)          // 4 chunks
#define NTX   (NP / TN)           // 32 tiles in x
#define NT    ((NP / TM) * NTX)   // 2048 tiles

// smem byte offsets: 4 resident chunks, 128B rows, XOR-16B swizzle
#define OFF_A(c)  ((c) * 16384)                  // 128 rows * 128B
#define OFF_B(c)  (65536 + (c) * 32768)          // 256 rows * 128B
#define OFF_SQA   196608                         // 128 floats (512B)
#define OFF_SQB   197120                         // 256 floats (1024B)
#define OFF_TKT   198144                         // ticket broadcast (16B)
#define SMEM_TOT  198160

#define FXSCALE   1099511627776.0                // 2^40

// ---------------- scratch (allocation-free rule) ----------------
__device__ float              g_sq1[NP];
__device__ float              g_sq2[NP];
__device__ unsigned           g_min1[NP];
__device__ unsigned           g_min2[NP];
__device__ __nv_bfloat16      g_b1[NP * DIM];
__device__ __nv_bfloat16      g_b2[NP * DIM];
__device__ unsigned long long g_fsum = 0;        // fixed-point sum (2^-40 units)
__device__ unsigned           g_done = 0;        // finalize ticket counter
__device__ unsigned           g_tile = 0;        // dynamic tile ticket counter

__device__ __forceinline__ uint32_t s2u(const void* p) {
    uint32_t a;
    asm("{ .reg .u64 t; cvta.to.shared.u64 t, %1; cvt.u32.u64 %0, t; }"
        : "=r"(a) : "l"(p));
    return a;
}
__device__ __forceinline__ void cp16(uint32_t dst, const void* src) {
    asm volatile("cp.async.cg.shared.global [%0], [%1], 16;"
                 :: "r"(dst), "l"(__cvta_generic_to_global(src)) : "memory");
}
__device__ __forceinline__ void ldm_x4(uint32_t& r0, uint32_t& r1,
                                       uint32_t& r2, uint32_t& r3, uint32_t a) {
    asm volatile("ldmatrix.sync.aligned.m8n8.x4.shared.b16 {%0,%1,%2,%3}, [%4];"
                 : "=r"(r0), "=r"(r1), "=r"(r2), "=r"(r3) : "r"(a));
}
__device__ __forceinline__ void mma16816(float& c0, float& c1, float& c2, float& c3,
                                         uint32_t a0, uint32_t a1, uint32_t a2, uint32_t a3,
                                         uint32_t b0, uint32_t b1) {
    asm volatile("mma.sync.aligned.m16n8k16.row.col.f32.bf16.bf16.f32 "
                 "{%0,%1,%2,%3}, {%4,%5,%6,%7}, {%8,%9}, {%0,%1,%2,%3};"
                 : "+f"(c0), "+f"(c1), "+f"(c2), "+f"(c3)
                 : "r"(a0), "r"(a1), "r"(a2), "r"(a3), "r"(b0), "r"(b1));
}

// ---------------------------------------------------------------------------
// Kernel 1: fp32 -> bf16 conversion + norms + min init. One warp per row.
// (identical to the round-13 winner)
// ---------------------------------------------------------------------------
__global__ void prep_kernel(const float* __restrict__ s1,
                            const float* __restrict__ s2) {
    int gw   = (blockIdx.x * blockDim.x + threadIdx.x) >> 5;
    int lane = threadIdx.x & 31;
    bool first = gw < NP;
    int row = gw & (NP - 1);
    const float4* p = reinterpret_cast<const float4*>(
        (first ? s1 : s2) + (size_t)row * DIM);
    uint4* dst = reinterpret_cast<uint4*>(
        (first ? g_b1 : g_b2) + (size_t)row * DIM);

    float4 v0 = p[2 * lane];
    float4 v1 = p[2 * lane + 1];
    float s = v0.x * v0.x + v0.y * v0.y + v0.z * v0.z + v0.w * v0.w
            + v1.x * v1.x + v1.y * v1.y + v1.z * v1.z + v1.w * v1.w;
    __nv_bfloat162 h0 = __float22bfloat162_rn(make_float2(v0.x, v0.y));
    __nv_bfloat162 h1 = __float22bfloat162_rn(make_float2(v0.z, v0.w));
    __nv_bfloat162 h2 = __float22bfloat162_rn(make_float2(v1.x, v1.y));
    __nv_bfloat162 h3 = __float22bfloat162_rn(make_float2(v1.z, v1.w));
    uint4 w;
    w.x = *reinterpret_cast<uint32_t*>(&h0);
    w.y = *reinterpret_cast<uint32_t*>(&h1);
    w.z = *reinterpret_cast<uint32_t*>(&h2);
    w.w = *reinterpret_cast<uint32_t*>(&h3);
    dst[lane] = w;

#pragma unroll
    for (int o = 16; o; o >>= 1) s += __shfl_xor_sync(0xffffffffu, s, o);
    if (lane == 0) {
        if (first) { g_sq1[row] = s; g_min1[row] = 0x7f7fffffu; }
        else       { g_sq2[row] = s; g_min2[row] = 0x7f7fffffu; }
    }
}

// ---------------------------------------------------------------------------
// Kernel 2: PERSISTENT bf16 HMMA Gram kernel with DYNAMIC tile tickets.
// Body/epilogue identical to round-13; only the tile schedule changed from
// static striding to an atomic ticket counter (bounds inter-SM skew to ~1
// tile instead of ~10% of the whole pass).
// ---------------------------------------------------------------------------
__global__ void __launch_bounds__(256, 1)
dist_min_mma_kernel() {
    extern __shared__ char smem[];
    const uint32_t sbp = s2u(smem);
    float* sqa_s = reinterpret_cast<float*>(smem + OFF_SQA);
    float* sqb_s = reinterpret_cast<float*>(smem + OFF_SQB);
    volatile int* tkt_s = reinterpret_cast<volatile int*>(smem + OFF_TKT);

    const int tid  = threadIdx.x;
    const int lane = tid & 31;
    const int wid  = tid >> 5;
    const int wm   = wid & 1;          // 64-row slice
    const int wn   = wid >> 1;         // 64-col slice

    auto issue_chunk = [&](int tile, int c) {
        int rb = (tile >> 5) * TM;
        int cb = (tile & (NTX - 1)) * TN;
        const __nv_bfloat16* ga = g_b1 + (size_t)rb * DIM + c * KC;
        const __nv_bfloat16* gb = g_b2 + (size_t)cb * DIM + c * KC;
        uint32_t da = sbp + OFF_A(c), db = sbp + OFF_B(c);
#pragma unroll
        for (int it = 0; it < 4; ++it) {
            int idx = tid + it * 256;           // 0..1023
            int r = idx >> 3, q = idx & 7;
            cp16(da + r * 128 + ((q ^ (r & 7)) << 4), ga + (size_t)r * DIM + q * 8);
        }
#pragma unroll
        for (int it = 0; it < 8; ++it) {
            int idx = tid + it * 256;           // 0..2047
            int r = idx >> 3, q = idx & 7;
            cp16(db + r * 128 + ((q ^ (r & 7)) << 4), gb + (size_t)r * DIM + q * 8);
        }
        asm volatile("cp.async.commit_group;" ::: "memory");
    };

    const int l7 = lane & 7;
    const int ah = lane >> 4;                    // A: 16B-slot half
    const int bh = (lane >> 3) & 1;              // B: 16B-slot half
    const uint32_t a_ro = (uint32_t)(wm * 64 + (lane & 15)) * 128;
    const uint32_t b_ro = (uint32_t)(wn * 64 + (lane & 7) + ((lane >> 4) << 3)) * 128;

    // ---- grab first tile ticket, fill the 4-chunk pipe ----
    if (tid == 0) tkt_s[0] = (int)atomicAdd(&g_tile, 1u);
    __syncthreads();
    int cur = tkt_s[0];
    if (cur >= NT) return;                       // G <= NT always here
#pragma unroll
    for (int c = 0; c < NKC; ++c) issue_chunk(cur, c);

    for (;;) {
        const int rowBase = (cur >> 5) * TM;
        const int colBase = (cur & (NTX - 1)) * TN;

        if (tid < 128) sqa_s[tid] = g_sq1[rowBase + tid];
        sqb_s[tid] = g_sq2[colBase + tid];
        if (tid == 0) tkt_s[0] = (int)atomicAdd(&g_tile, 1u);  // next ticket

        float acc[4][8][4];
#pragma unroll
        for (int i = 0; i < 4; ++i)
#pragma unroll
            for (int j = 0; j < 8; ++j)
#pragma unroll
                for (int q = 0; q < 4; ++q) acc[i][j][q] = 0.f;

        int nxt = NT, nxt_c = cur;               // set after first sync
#pragma unroll
        for (int c = 0; c < NKC; ++c) {
            asm volatile("cp.async.wait_group 3;" ::: "memory");
            __syncthreads();
            if (c == 0) {                        // ticket now visible to all
                nxt = tkt_s[0];
                nxt_c = (nxt < NT) ? nxt : cur;  // re-issue self keeps counts uniform
            }

            const uint32_t sa0 = sbp + OFF_A(c) + a_ro;
            const uint32_t sb0 = sbp + OFF_B(c) + b_ro;
#pragma unroll
            for (int ks = 0; ks < 4; ++ks) {
                const uint32_t swa = (uint32_t)(((2 * ks + ah) ^ l7) << 4);
                const uint32_t swb = (uint32_t)(((2 * ks + bh) ^ l7) << 4);
                uint32_t a[4][4], bb[4][4];
#pragma unroll
                for (int mt = 0; mt < 4; ++mt)
                    ldm_x4(a[mt][0], a[mt][1], a[mt][2], a[mt][3],
                           sa0 + mt * 16 * 128 + swa);
#pragma unroll
                for (int np = 0; np < 4; ++np)
                    ldm_x4(bb[np][0], bb[np][1], bb[np][2], bb[np][3],
                           sb0 + np * 16 * 128 + swb);
#pragma unroll
                for (int mt = 0; mt < 4; ++mt)
#pragma unroll
                    for (int np = 0; np < 4; ++np) {
                        mma16816(acc[mt][2 * np][0], acc[mt][2 * np][1],
                                 acc[mt][2 * np][2], acc[mt][2 * np][3],
                                 a[mt][0], a[mt][1], a[mt][2], a[mt][3],
                                 bb[np][0], bb[np][1]);
                        mma16816(acc[mt][2 * np + 1][0], acc[mt][2 * np + 1][1],
                                 acc[mt][2 * np + 1][2], acc[mt][2 * np + 1][3],
                                 a[mt][0], a[mt][1], a[mt][2], a[mt][3],
                                 bb[np][2], bb[np][3]);
                    }
            }
            __syncthreads();
            issue_chunk(nxt_c, c);
        }

        // ---- Epilogue: d^2 + fused row/col mins ----
        const float FMAX = 3.4028235e38f;
        float rmin[4][2];
#pragma unroll
        for (int i = 0; i < 4; ++i) rmin[i][0] = rmin[i][1] = FMAX;
        float cmin[8][2];
#pragma unroll
        for (int j = 0; j < 8; ++j) cmin[j][0] = cmin[j][1] = FMAX;

#pragma unroll
        for (int mt = 0; mt < 4; ++mt) {
            float sqa0 = sqa_s[wm * 64 + mt * 16 + (lane >> 2)];
            float sqa1 = sqa_s[wm * 64 + mt * 16 + (lane >> 2) + 8];
#pragma unroll
            for (int n8 = 0; n8 < 8; ++n8) {
                float sqb0 = sqb_s[wn * 64 + n8 * 8 + 2 * (lane & 3)];
                float sqb1 = sqb_s[wn * 64 + n8 * 8 + 2 * (lane & 3) + 1];
                float d00 = fmaxf(fmaf(-2.f, acc[mt][n8][0], sqa0 + sqb0), 0.f);
                float d01 = fmaxf(fmaf(-2.f, acc[mt][n8][1], sqa0 + sqb1), 0.f);
                float d10 = fmaxf(fmaf(-2.f, acc[mt][n8][2], sqa1 + sqb0), 0.f);
                float d11 = fmaxf(fmaf(-2.f, acc[mt][n8][3], sqa1 + sqb1), 0.f);
                rmin[mt][0] = fminf(rmin[mt][0], fminf(d00, d01));
                rmin[mt][1] = fminf(rmin[mt][1], fminf(d10, d11));
                cmin[n8][0] = fminf(cmin[n8][0], fminf(d00, d10));
                cmin[n8][1] = fminf(cmin[n8][1], fminf(d01, d11));
            }
        }

#pragma unroll
        for (int mt = 0; mt < 4; ++mt)
#pragma unroll
            for (int hh = 0; hh < 2; ++hh) {
                float v = rmin[mt][hh];
                v = fminf(v, __shfl_xor_sync(0xffffffffu, v, 1));
                v = fminf(v, __shfl_xor_sync(0xffffffffu, v, 2));
                if ((lane & 3) == 0)
                    atomicMin(&g_min1[rowBase + wm * 64 + mt * 16 + hh * 8 + (lane >> 2)],
                              __float_as_uint(v));
            }

#pragma unroll
        for (int n8 = 0; n8 < 8; ++n8)
#pragma unroll
            for (int q = 0; q < 2; ++q) {
                float v = cmin[n8][q];
                v = fminf(v, __shfl_xor_sync(0xffffffffu, v, 4));
                v = fminf(v, __shfl_xor_sync(0xffffffffu, v, 8));
                v = fminf(v, __shfl_xor_sync(0xffffffffu, v, 16));
                if (lane < 4)
                    atomicMin(&g_min2[colBase + wn * 64 + n8 * 8 + 2 * lane + q],
                              __float_as_uint(v));
            }

        __syncthreads();   // protect sqa_s/sqb_s + tkt_s (rewritten next iter)
        if (nxt >= NT) break;
        cur = nxt;
    }

    asm volatile("cp.async.wait_group 0;" ::: "memory");  // drain before exit
}

// ---------------------------------------------------------------------------
// Kernel 3: parallel finalize (round-13 winner) + ticket counter resets.
// ---------------------------------------------------------------------------
__global__ void finalize_kernel(float* __restrict__ out) {
    __shared__ float red[8];
    const int tid = threadIdx.x;
    const int gid = blockIdx.x * 256 + tid;      // 0..16383
    float v = (gid < NP) ? sqrtf(__uint_as_float(g_min1[gid]))
                         : sqrtf(__uint_as_float(g_min2[gid - NP]));
#pragma unroll
    for (int o = 16; o; o >>= 1) v += __shfl_xor_sync(0xffffffffu, v, o);
    if ((tid & 31) == 0) red[tid >> 5] = v;
    __syncthreads();
    if (tid < 32) {
        float s = (tid < 8) ? red[tid] : 0.f;
#pragma unroll
        for (int o = 4; o; o >>= 1) s += __shfl_xor_sync(0xffffffffu, s, o);
        if (tid == 0) {
            unsigned long long fx =
                (unsigned long long)((double)s * FXSCALE + 0.5);
            atomicAdd(&g_fsum, fx);
            __threadfence();
            unsigned ticket = atomicAdd(&g_done, 1u);
            if (ticket == gridDim.x - 1) {
                unsigned long long tot = atomicAdd(&g_fsum, 0ull);
                out[0] = (float)((double)tot / FXSCALE / (double)NP);
                g_fsum = 0ull;                  // reset for next replay
                g_done = 0u;
                g_tile = 0u;
            }
        }
    }
}

// ---------------------------------------------------------------------------
extern "C" void kernel_launch(void* const* d_in, const int* in_sizes, int n_in,
                              void* d_out, int out_size) {
    const float* s1 = (const float*)d_in[0];
    const float* s2 = (const float*)d_in[1];

    static int nsm = 0;
    if (nsm == 0) {
        cudaFuncSetAttribute(dist_min_mma_kernel,
                             cudaFuncAttributeMaxDynamicSharedMemorySize, SMEM_TOT);
        cudaDeviceGetAttribute(&nsm, cudaDevAttrMultiProcessorCount, 0);
        if (nsm <= 0) nsm = 148;
    }

    prep_kernel<<<2 * NP / 8, 256>>>(s1, s2);

    dist_min_mma_kernel<<<nsm, 256, SMEM_TOT>>>();

    finalize_kernel<<<2 * NP / 256, 256>>>((float*)d_out);
}

// round 17
// speedup vs baseline: 1.1875x; 1.0396x over previous
#include <cuda_runtime.h>
#include <cuda_bf16.h>
#include <cstdint>

#define NP    8192
#define DIM   256
#define TM    128                 // tile rows
#define TN    256                 // tile cols
#define KC    64                  // bf16 K-chunk: 128B rows
#define NKC   (DIM / KC)          // 4 chunks
#define NTX   (NP / TN)           // 32 tiles in x
#define NT    ((NP / TM) * NTX)   // 2048 tiles

// smem byte offsets: 4 resident chunks, 128B rows, XOR-16B swizzle
#define OFF_A(c)  ((c) * 16384)                  // 128 rows * 128B
#define OFF_B(c)  (65536 + (c) * 32768)          // 256 rows * 128B
#define OFF_SQA   196608                         // 128 floats (512B)
#define OFF_SQB   197120                         // 256 floats (1024B)
#define SMEM_TOT  198144

#define FXSCALE   1099511627776.0                // 2^40

// ---------------- scratch (allocation-free rule) ----------------
__device__ float              g_sq1[NP];
__device__ float              g_sq2[NP];
__device__ unsigned           g_min1[NP];
__device__ unsigned           g_min2[NP];
__device__ __nv_bfloat16      g_b1[NP * DIM];
__device__ __nv_bfloat16      g_b2[NP * DIM];
__device__ unsigned long long g_fsum = 0;        // fixed-point sum (2^-40 units)
__device__ unsigned           g_done = 0;        // finalize ticket counter

__device__ __forceinline__ uint32_t s2u(const void* p) {
    uint32_t a;
    asm("{ .reg .u64 t; cvta.to.shared.u64 t, %1; cvt.u32.u64 %0, t; }"
        : "=r"(a) : "l"(p));
    return a;
}
__device__ __forceinline__ void cp16(uint32_t dst, const void* src) {
    asm volatile("cp.async.cg.shared.global [%0], [%1], 16;"
                 :: "r"(dst), "l"(__cvta_generic_to_global(src)) : "memory");
}
__device__ __forceinline__ void ldm_x4(uint32_t& r0, uint32_t& r1,
                                       uint32_t& r2, uint32_t& r3, uint32_t a) {
    asm volatile("ldmatrix.sync.aligned.m8n8.x4.shared.b16 {%0,%1,%2,%3}, [%4];"
                 : "=r"(r0), "=r"(r1), "=r"(r2), "=r"(r3) : "r"(a));
}
__device__ __forceinline__ void mma16816(float& c0, float& c1, float& c2, float& c3,
                                         uint32_t a0, uint32_t a1, uint32_t a2, uint32_t a3,
                                         uint32_t b0, uint32_t b1) {
    asm volatile("mma.sync.aligned.m16n8k16.row.col.f32.bf16.bf16.f32 "
                 "{%0,%1,%2,%3}, {%4,%5,%6,%7}, {%8,%9}, {%0,%1,%2,%3};"
                 : "+f"(c0), "+f"(c1), "+f"(c2), "+f"(c3)
                 : "r"(a0), "r"(a1), "r"(a2), "r"(a3), "r"(b0), "r"(b1));
}

// ---------------------------------------------------------------------------
// Kernel 1: fp32 -> bf16 conversion + norms + min init. One warp per row.
// ---------------------------------------------------------------------------
__global__ void prep_kernel(const float* __restrict__ s1,
                            const float* __restrict__ s2) {
    int gw   = (blockIdx.x * blockDim.x + threadIdx.x) >> 5;
    int lane = threadIdx.x & 31;
    bool first = gw < NP;
    int row = gw & (NP - 1);
    const float4* p = reinterpret_cast<const float4*>(
        (first ? s1 : s2) + (size_t)row * DIM);
    uint4* dst = reinterpret_cast<uint4*>(
        (first ? g_b1 : g_b2) + (size_t)row * DIM);

    float4 v0 = p[2 * lane];
    float4 v1 = p[2 * lane + 1];
    float s = v0.x * v0.x + v0.y * v0.y + v0.z * v0.z + v0.w * v0.w
            + v1.x * v1.x + v1.y * v1.y + v1.z * v1.z + v1.w * v1.w;
    __nv_bfloat162 h0 = __float22bfloat162_rn(make_float2(v0.x, v0.y));
    __nv_bfloat162 h1 = __float22bfloat162_rn(make_float2(v0.z, v0.w));
    __nv_bfloat162 h2 = __float22bfloat162_rn(make_float2(v1.x, v1.y));
    __nv_bfloat162 h3 = __float22bfloat162_rn(make_float2(v1.z, v1.w));
    uint4 w;
    w.x = *reinterpret_cast<uint32_t*>(&h0);
    w.y = *reinterpret_cast<uint32_t*>(&h1);
    w.z = *reinterpret_cast<uint32_t*>(&h2);
    w.w = *reinterpret_cast<uint32_t*>(&h3);
    dst[lane] = w;

#pragma unroll
    for (int o = 16; o; o >>= 1) s += __shfl_xor_sync(0xffffffffu, s, o);
    if (lane == 0) {
        if (first) { g_sq1[row] = s; g_min1[row] = 0x7f7fffffu; }
        else       { g_sq2[row] = s; g_min2[row] = 0x7f7fffffu; }
    }
}

// ---------------------------------------------------------------------------
// Kernel 2: PERSISTENT bf16 HMMA Gram kernel. Each CTA loops over tiles
// (static stride — preserves implicit L2 A-block sharing), prefetching tile
// t+G's chunk c into the buffer tile t's chunk c just finished reading.
// 8 warps (2x4), 64x64 warp tile, fused min epilogue.
// ---------------------------------------------------------------------------
__global__ void __launch_bounds__(256, 1)
dist_min_mma_kernel() {
    extern __shared__ char smem[];
    const uint32_t sbp = s2u(smem);
    float* sqa_s = reinterpret_cast<float*>(smem + OFF_SQA);
    float* sqb_s = reinterpret_cast<float*>(smem + OFF_SQB);

    const int tid  = threadIdx.x;
    const int lane = tid & 31;
    const int wid  = tid >> 5;
    const int wm   = wid & 1;          // 64-row slice
    const int wn   = wid >> 1;         // 64-col slice
    const int G    = gridDim.x;

    auto issue_chunk = [&](int tile, int c) {
        int rb = (tile >> 5) * TM;
        int cb = (tile & (NTX - 1)) * TN;
        const __nv_bfloat16* ga = g_b1 + (size_t)rb * DIM + c * KC;
        const __nv_bfloat16* gb = g_b2 + (size_t)cb * DIM + c * KC;
        uint32_t da = sbp + OFF_A(c), db = sbp + OFF_B(c);
#pragma unroll
        for (int it = 0; it < 4; ++it) {
            int idx = tid + it * 256;           // 0..1023
            int r = idx >> 3, q = idx & 7;
            cp16(da + r * 128 + ((q ^ (r & 7)) << 4), ga + (size_t)r * DIM + q * 8);
        }
#pragma unroll
        for (int it = 0; it < 8; ++it) {
            int idx = tid + it * 256;           // 0..2047
            int r = idx >> 3, q = idx & 7;
            cp16(db + r * 128 + ((q ^ (r & 7)) << 4), gb + (size_t)r * DIM + q * 8);
        }
        asm volatile("cp.async.commit_group;" ::: "memory");
    };

    const int l7 = lane & 7;
    const int ah = lane >> 4;                    // A: 16B-slot half
    const int bh = (lane >> 3) & 1;              // B: 16B-slot half
    const uint32_t a_ro = (uint32_t)(wm * 64 + (lane & 15)) * 128;
    const uint32_t b_ro = (uint32_t)(wn * 64 + (lane & 7) + ((lane >> 4) << 3)) * 128;

#pragma unroll
    for (int c = 0; c < NKC; ++c) issue_chunk(blockIdx.x, c);

    for (int t = blockIdx.x; t < NT; t += G) {
        const int rowBase = (t >> 5) * TM;
        const int colBase = (t & (NTX - 1)) * TN;
        int nt = t + G;
        if (nt >= NT) nt = t;                    // keep group-count math uniform

        if (tid < 128) sqa_s[tid] = g_sq1[rowBase + tid];
        sqb_s[tid] = g_sq2[colBase + tid];

        float acc[4][8][4];
#pragma unroll
        for (int i = 0; i < 4; ++i)
#pragma unroll
            for (int j = 0; j < 8; ++j)
#pragma unroll
                for (int q = 0; q < 4; ++q) acc[i][j][q] = 0.f;

#pragma unroll
        for (int c = 0; c < NKC; ++c) {
            asm volatile("cp.async.wait_group 3;" ::: "memory");
            __syncthreads();

            const uint32_t sa0 = sbp + OFF_A(c) + a_ro;
            const uint32_t sb0 = sbp + OFF_B(c) + b_ro;
#pragma unroll
            for (int ks = 0; ks < 4; ++ks) {
                const uint32_t swa = (uint32_t)(((2 * ks + ah) ^ l7) << 4);
                const uint32_t swb = (uint32_t)(((2 * ks + bh) ^ l7) << 4);
                uint32_t a[4][4], bb[4][4];
#pragma unroll
                for (int mt = 0; mt < 4; ++mt)
                    ldm_x4(a[mt][0], a[mt][1], a[mt][2], a[mt][3],
                           sa0 + mt * 16 * 128 + swa);
#pragma unroll
                for (int np = 0; np < 4; ++np)
                    ldm_x4(bb[np][0], bb[np][1], bb[np][2], bb[np][3],
                           sb0 + np * 16 * 128 + swb);
#pragma unroll
                for (int mt = 0; mt < 4; ++mt)
#pragma unroll
                    for (int np = 0; np < 4; ++np) {
                        mma16816(acc[mt][2 * np][0], acc[mt][2 * np][1],
                                 acc[mt][2 * np][2], acc[mt][2 * np][3],
                                 a[mt][0], a[mt][1], a[mt][2], a[mt][3],
                                 bb[np][0], bb[np][1]);
                        mma16816(acc[mt][2 * np + 1][0], acc[mt][2 * np + 1][1],
                                 acc[mt][2 * np + 1][2], acc[mt][2 * np + 1][3],
                                 a[mt][0], a[mt][1], a[mt][2], a[mt][3],
                                 bb[np][2], bb[np][3]);
                    }
            }
            __syncthreads();
            issue_chunk(nt, c);
        }

        // ---- Epilogue: d^2 + fused row/col mins ----
        const float FMAX = 3.4028235e38f;
        float rmin[4][2];
#pragma unroll
        for (int i = 0; i < 4; ++i) rmin[i][0] = rmin[i][1] = FMAX;
        float cmin[8][2];
#pragma unroll
        for (int j = 0; j < 8; ++j) cmin[j][0] = cmin[j][1] = FMAX;

#pragma unroll
        for (int mt = 0; mt < 4; ++mt) {
            float sqa0 = sqa_s[wm * 64 + mt * 16 + (lane >> 2)];
            float sqa1 = sqa_s[wm * 64 + mt * 16 + (lane >> 2) + 8];
#pragma unroll
            for (int n8 = 0; n8 < 8; ++n8) {
                float sqb0 = sqb_s[wn * 64 + n8 * 8 + 2 * (lane & 3)];
                float sqb1 = sqb_s[wn * 64 + n8 * 8 + 2 * (lane & 3) + 1];
                float d00 = fmaxf(fmaf(-2.f, acc[mt][n8][0], sqa0 + sqb0), 0.f);
                float d01 = fmaxf(fmaf(-2.f, acc[mt][n8][1], sqa0 + sqb1), 0.f);
                float d10 = fmaxf(fmaf(-2.f, acc[mt][n8][2], sqa1 + sqb0), 0.f);
                float d11 = fmaxf(fmaf(-2.f, acc[mt][n8][3], sqa1 + sqb1), 0.f);
                rmin[mt][0] = fminf(rmin[mt][0], fminf(d00, d01));
                rmin[mt][1] = fminf(rmin[mt][1], fminf(d10, d11));
                cmin[n8][0] = fminf(cmin[n8][0], fminf(d00, d10));
                cmin[n8][1] = fminf(cmin[n8][1], fminf(d01, d11));
            }
        }

#pragma unroll
        for (int mt = 0; mt < 4; ++mt)
#pragma unroll
            for (int hh = 0; hh < 2; ++hh) {
                float v = rmin[mt][hh];
                v = fminf(v, __shfl_xor_sync(0xffffffffu, v, 1));
                v = fminf(v, __shfl_xor_sync(0xffffffffu, v, 2));
                if ((lane & 3) == 0)
                    atomicMin(&g_min1[rowBase + wm * 64 + mt * 16 + hh * 8 + (lane >> 2)],
                              __float_as_uint(v));
            }

#pragma unroll
        for (int n8 = 0; n8 < 8; ++n8)
#pragma unroll
            for (int q = 0; q < 2; ++q) {
                float v = cmin[n8][q];
                v = fminf(v, __shfl_xor_sync(0xffffffffu, v, 4));
                v = fminf(v, __shfl_xor_sync(0xffffffffu, v, 8));
                v = fminf(v, __shfl_xor_sync(0xffffffffu, v, 16));
                if (lane < 4)
                    atomicMin(&g_min2[colBase + wn * 64 + n8 * 8 + 2 * lane + q],
                              __float_as_uint(v));
            }

        __syncthreads();   // protect sqa_s/sqb_s (rewritten next iteration)
    }

    asm volatile("cp.async.wait_group 0;" ::: "memory");  // drain before exit
}

// ---------------------------------------------------------------------------
// Kernel 3: parallel finalize. 64 CTAs x 256 threads, one element each.
// Deterministic: per-block fp32 tree sum -> 2^40 fixed-point u64 atomicAdd.
// Last-arriving block writes out and resets accumulators for graph replay.
// ---------------------------------------------------------------------------
__global__ void finalize_kernel(float* __restrict__ out) {
    __shared__ float red[8];
    const int tid = threadIdx.x;
    const int gid = blockIdx.x * 256 + tid;      // 0..16383
    float v = (gid < NP) ? sqrtf(__uint_as_float(g_min1[gid]))
                         : sqrtf(__uint_as_float(g_min2[gid - NP]));
#pragma unroll
    for (int o = 16; o; o >>= 1) v += __shfl_xor_sync(0xffffffffu, v, o);
    if ((tid & 31) == 0) red[tid >> 5] = v;
    __syncthreads();
    if (tid < 32) {
        float s = (tid < 8) ? red[tid] : 0.f;
#pragma unroll
        for (int o = 4; o; o >>= 1) s += __shfl_xor_sync(0xffffffffu, s, o);
        if (tid == 0) {
            unsigned long long fx =
                (unsigned long long)((double)s * FXSCALE + 0.5);
            atomicAdd(&g_fsum, fx);
            __threadfence();
            unsigned ticket = atomicAdd(&g_done, 1u);
            if (ticket == gridDim.x - 1) {
                unsigned long long tot = atomicAdd(&g_fsum, 0ull);
                out[0] = (float)((double)tot / FXSCALE / (double)NP);
                g_fsum = 0ull;                  // reset for next replay
                g_done = 0u;
            }
        }
    }
}

// ---------------------------------------------------------------------------
extern "C" void kernel_launch(void* const* d_in, const int* in_sizes, int n_in,
                              void* d_out, int out_size) {
    const float* s1 = (const float*)d_in[0];
    const float* s2 = (const float*)d_in[1];

    static int nsm = 0;
    if (nsm == 0) {
        cudaFuncSetAttribute(dist_min_mma_kernel,
                             cudaFuncAttributeMaxDynamicSharedMemorySize, SMEM_TOT);
        cudaDeviceGetAttribute(&nsm, cudaDevAttrMultiProcessorCount, 0);
        if (nsm <= 0) nsm = 148;
    }

    prep_kernel<<<2 * NP / 8, 256>>>(s1, s2);

    dist_min_mma_kernel<<<nsm, 256, SMEM_TOT>>>();

    finalize_kernel<<<2 * NP / 256, 256>>>((float*)d_out);
}